// round 7
// baseline (speedup 1.0000x reference)
#include <cuda_runtime.h>
#include <cuda_bf16.h>
#include <math.h>
#include <stdint.h>

#define NEG_INF_F (-1e30f)

static constexpr int B = 64;
static constexpr int C = 1024;
static constexpr int Q = 128;
static constexpr int H = 512;
static constexpr int NCH = 32;

// ---------------- scratch (device globals: allocation-free rule) ----------------
__device__ float g_qw[(size_t)B * Q * H];      // tf32(xq*W2)
__device__ float g_xqR[(size_t)B * Q * H];     // tf32(x_query)
__device__ float g_xcR[(size_t)B * C * H];     // tf32(x_context)
__device__ float g_sub0[B * Q];
__device__ float g_sub1[B * C];
__device__ float g_S[(size_t)B * C * Q];       // S, then tf32(S_) in place
__device__ float g_Sc[(size_t)B * C * Q];      // tf32(softmax over c)
__device__ float g_tmp[(size_t)B * Q * H];     // tf32(S_c^T @ Xc)
__device__ float g_pm[B * NCH * Q];
__device__ float g_ps[B * NCH * Q];
__device__ float g_gm[B * Q];
__device__ float g_ginv[B * Q];

// ---------------- helpers ----------------
__device__ __forceinline__ float to_tf32(float x) {
    asm("cvt.rna.tf32.f32 %0, %1;" : "=f"(x) : "f"(x));
    return x;
}

__device__ __forceinline__ void mma_tf32(float* c, const unsigned* a, const unsigned* b) {
    asm volatile(
        "mma.sync.aligned.m16n8k8.row.col.f32.tf32.tf32.f32 "
        "{%0,%1,%2,%3}, {%4,%5,%6,%7}, {%8,%9}, {%0,%1,%2,%3};"
        : "+f"(c[0]), "+f"(c[1]), "+f"(c[2]), "+f"(c[3])
        : "r"(a[0]), "r"(a[1]), "r"(a[2]), "r"(a[3]), "r"(b[0]), "r"(b[1]));
}

__device__ __forceinline__ float block_reduce_sum_128(float v, float* red) {
    int t = threadIdx.x;
    #pragma unroll
    for (int o = 16; o > 0; o >>= 1) v += __shfl_xor_sync(0xffffffffu, v, o);
    if ((t & 31) == 0) red[t >> 5] = v;
    __syncthreads();
    return red[0] + red[1] + red[2] + red[3];
}

// ---------------- fused prep (one launch):
// blocks [0, B*Q): qw = tf32(xq*W2), xqR = tf32(xq), sub0 = dot(xq,W0)
// blocks [B*Q, B*Q + B*C): xcR = tf32(xc), sub1 = dot(xc,W1)
__global__ void prep_kernel(const float* __restrict__ xq, const float* __restrict__ xc,
                            const float* __restrict__ W0, const float* __restrict__ W1,
                            const float* __restrict__ W2,
                            float* __restrict__ qw, float* __restrict__ xqR,
                            float* __restrict__ xcR,
                            float* __restrict__ sub0, float* __restrict__ sub1) {
    int blk = blockIdx.x;
    int t = threadIdx.x;
    __shared__ float red[4];
    if (blk < B * Q) {
        const float* row = xq + (size_t)blk * H;
        float* o1 = qw + (size_t)blk * H;
        float* o2 = xqR + (size_t)blk * H;
        float s = 0.f;
        #pragma unroll
        for (int i = 0; i < H / 128; i++) {
            int h = i * 128 + t;
            float v = row[h];
            o1[h] = to_tf32(v * W2[h]);
            o2[h] = to_tf32(v);
            s = fmaf(v, W0[h], s);
        }
        s = block_reduce_sum_128(s, red);
        if (t == 0) sub0[blk] = s;
    } else {
        int bc = blk - B * Q;
        const float* row = xc + (size_t)bc * H;
        float* o = xcR + (size_t)bc * H;
        float s = 0.f;
        #pragma unroll
        for (int i = 0; i < H / 128; i++) {
            int h = i * 128 + t;
            float v = row[h];
            o[h] = to_tf32(v);
            s = fmaf(v, W1[h], s);
        }
        s = block_reduce_sum_128(s, red);
        if (t == 0) sub1[bc] = s;
    }
}

// ---------------- tf32 mma.sync GEMM: pair-layout smem, reg-staged double buffer ----------------
// D[m,n] = sum_k A(m,k)*B(n,k) (+rowBias[m] + colBias[n] + *scalarBias)
// AMODE 0: A row-major MxK; AMODE 1: A row-major KxM. Same for BMODE over N/K.
// All operands MUST be pre-rounded to tf32 (no cvt in this kernel).
// Tile 128x128x16, 8 warps, warp tile 64x32.
// Pair layout: plane[ks][row][slot], slot(k) = (k&3)*2 + ((k>>2)&1) for k in 0..7;
// fragment pair (k=tg, k=tg+4) -> one float2 at slot tg*2.
template <int AMODE, int BMODE, int ROUND_OUT>
__global__ void __launch_bounds__(256)
gemm_tf32_kernel(const float* __restrict__ A, const float* __restrict__ Bp,
                 float* __restrict__ Cp, int K,
                 int lda, int ldb, int ldc,
                 size_t sA, size_t sB, size_t sC,
                 const float* __restrict__ rowBias, int rbStride,
                 const float* __restrict__ colBias, int cbStride,
                 const float* __restrict__ scalarBias) {
    __shared__ float As2[2][2][128][8];
    __shared__ float Bs2[2][2][128][8];

    const int bz = blockIdx.z;
    A  += (size_t)bz * sA;
    Bp += (size_t)bz * sB;
    Cp += (size_t)bz * sC;
    const int tileM = blockIdx.y * 128;
    const int tileN = blockIdx.x * 128;
    const int tid = threadIdx.x;
    const int wid = tid >> 5, lane = tid & 31;
    const int warpM = (wid & 1) * 64;
    const int warpN = (wid >> 1) * 32;
    const int g = lane >> 2, tg = lane & 3;

    int am[2], ak[2], bn[2], bk[2];
    #pragma unroll
    for (int t = 0; t < 2; t++) {
        int i = tid + t * 256;
        if (AMODE == 0) { am[t] = i >> 2;  ak[t] = (i & 3) * 4; }
        else            { ak[t] = i >> 5;  am[t] = (i & 31) * 4; }
        if (BMODE == 0) { bn[t] = i >> 2;  bk[t] = (i & 3) * 4; }
        else            { bk[t] = i >> 5;  bn[t] = (i & 31) * 4; }
    }

    float4 ra[2], rb[2];
    auto ldg = [&](int k0) {
        #pragma unroll
        for (int t = 0; t < 2; t++) {
            ra[t] = (AMODE == 0)
                ? *(const float4*)(A + (size_t)(tileM + am[t]) * lda + k0 + ak[t])
                : *(const float4*)(A + (size_t)(k0 + ak[t]) * lda + tileM + am[t]);
            rb[t] = (BMODE == 0)
                ? *(const float4*)(Bp + (size_t)(tileN + bn[t]) * ldb + k0 + bk[t])
                : *(const float4*)(Bp + (size_t)(k0 + bk[t]) * ldb + tileN + bn[t]);
        }
    };
    auto sts = [&](int st) {
        #pragma unroll
        for (int t = 0; t < 2; t++) {
            float va[4] = {ra[t].x, ra[t].y, ra[t].z, ra[t].w};
            float vb[4] = {rb[t].x, rb[t].y, rb[t].z, rb[t].w};
            #pragma unroll
            for (int j = 0; j < 4; j++) {
                int ka = (AMODE == 0) ? ak[t] + j : ak[t];
                int ma = (AMODE == 0) ? am[t] : am[t] + j;
                As2[st][(ka >> 3) & 1][ma][(ka & 3) * 2 + ((ka >> 2) & 1)] = va[j];
                int kb = (BMODE == 0) ? bk[t] + j : bk[t];
                int nb = (BMODE == 0) ? bn[t] : bn[t] + j;
                Bs2[st][(kb >> 3) & 1][nb][(kb & 3) * 2 + ((kb >> 2) & 1)] = vb[j];
            }
        }
    };

    float acc[4][4][4] = {};
    const int nIter = K >> 4;

    ldg(0);
    sts(0);
    ldg(16);                 // regs now hold iter-1 data
    int st = 0;

    for (int it = 0; it < nIter; it++) {
        __syncthreads();
        const bool more = (it + 1) < nIter;

        #pragma unroll
        for (int ks = 0; ks < 2; ks++) {
            float2 a2[4][2], b2[4];
            #pragma unroll
            for (int mt = 0; mt < 4; mt++) {
                int m0 = warpM + mt * 16 + g;
                a2[mt][0] = *(const float2*)&As2[st][ks][m0    ][tg * 2];
                a2[mt][1] = *(const float2*)&As2[st][ks][m0 + 8][tg * 2];
            }
            #pragma unroll
            for (int nt = 0; nt < 4; nt++)
                b2[nt] = *(const float2*)&Bs2[st][ks][warpN + nt * 8 + g][tg * 2];
            #pragma unroll
            for (int mt = 0; mt < 4; mt++) {
                unsigned af[4] = {__float_as_uint(a2[mt][0].x), __float_as_uint(a2[mt][1].x),
                                  __float_as_uint(a2[mt][0].y), __float_as_uint(a2[mt][1].y)};
                #pragma unroll
                for (int nt = 0; nt < 4; nt++) {
                    unsigned bf[2] = {__float_as_uint(b2[nt].x), __float_as_uint(b2[nt].y)};
                    mma_tf32(acc[mt][nt], af, bf);
                }
            }
        }
        if (more) {
            sts(st ^ 1);                       // store iter+1 (held in regs)
            if (it + 2 < nIter) ldg((it + 2) << 4);
        }
        st ^= 1;
    }

    // ---- epilogue ----
    const float sb = scalarBias ? __ldg(scalarBias) : 0.f;
    #pragma unroll
    for (int mt = 0; mt < 4; mt++) {
        int r0 = tileM + warpM + mt * 16 + g;
        int r1 = r0 + 8;
        float rb0 = rowBias ? rowBias[bz * rbStride + r0] + sb : sb;
        float rb1 = rowBias ? rowBias[bz * rbStride + r1] + sb : sb;
        #pragma unroll
        for (int nt = 0; nt < 4; nt++) {
            int c0 = tileN + warpN + nt * 8 + tg * 2;
            float cb0 = colBias ? colBias[bz * cbStride + c0    ] : 0.f;
            float cb1 = colBias ? colBias[bz * cbStride + c0 + 1] : 0.f;
            float w0 = acc[mt][nt][0] + rb0 + cb0;
            float w1 = acc[mt][nt][1] + rb0 + cb1;
            float w2 = acc[mt][nt][2] + rb1 + cb0;
            float w3 = acc[mt][nt][3] + rb1 + cb1;
            if (ROUND_OUT) { w0 = to_tf32(w0); w1 = to_tf32(w1); w2 = to_tf32(w2); w3 = to_tf32(w3); }
            Cp[(size_t)r0 * ldc + c0    ] = w0;
            Cp[(size_t)r0 * ldc + c0 + 1] = w1;
            Cp[(size_t)r1 * ldc + c0    ] = w2;
            Cp[(size_t)r1 * ldc + c0 + 1] = w3;
        }
    }
}

// ---------------- softmax over c (axis=1): partial + combine ----------------
__global__ void softc_partial(const float* __restrict__ S,
                              const float* __restrict__ cmask,
                              float* __restrict__ pm, float* __restrict__ ps) {
    int chunk = blockIdx.x, b = blockIdx.y;
    int q = threadIdx.x;
    constexpr int RB = C / NCH;
    const float* Sb = S + ((size_t)b * C + chunk * RB) * Q + q;
    const float* mcb = cmask + (size_t)b * C + chunk * RB;
    float m = -INFINITY, s = 0.f;
    #pragma unroll 4
    for (int c = 0; c < RB; c++) {
        float v = Sb[(size_t)c * Q] + (1.f - mcb[c]) * NEG_INF_F;
        float mn = fmaxf(m, v);
        s = s * __expf(m - mn) + __expf(v - mn);
        m = mn;
    }
    pm[(b * NCH + chunk) * Q + q] = m;
    ps[(b * NCH + chunk) * Q + q] = s;
}

__global__ void softc_combine(const float* __restrict__ pm,
                              const float* __restrict__ ps,
                              float* __restrict__ gm, float* __restrict__ ginv) {
    int b = blockIdx.x, q = threadIdx.x;
    float m = -INFINITY;
    #pragma unroll
    for (int ch = 0; ch < NCH; ch++)
        m = fmaxf(m, pm[(b * NCH + ch) * Q + q]);
    float s = 0.f;
    #pragma unroll
    for (int ch = 0; ch < NCH; ch++)
        s += ps[(b * NCH + ch) * Q + q] * __expf(pm[(b * NCH + ch) * Q + q] - m);
    gm[b * Q + q] = m;
    ginv[b * Q + q] = 1.f / s;
}

// ---------------- fused: softmax_q (in place, tf32) + softc write (Sc, tf32) ----------------
__global__ void fused_post(float* __restrict__ S,
                           float* __restrict__ Sc,
                           const float* __restrict__ cmask,
                           const float* __restrict__ qmask,
                           const float* __restrict__ gm,
                           const float* __restrict__ ginv) {
    int b = blockIdx.y;
    int c = blockIdx.x * 8 + (threadIdx.x >> 5);
    int lane = threadIdx.x & 31;
    size_t base = ((size_t)b * C + c) * Q;
    float cadd = (1.f - cmask[b * C + c]) * NEG_INF_F;

    float raw[4], v[4];
    #pragma unroll
    for (int i = 0; i < 4; i++) {
        int q = lane + i * 32;
        raw[i] = S[base + q];
        v[i] = raw[i] + (1.f - qmask[b * Q + q]) * NEG_INF_F;
    }
    float m = fmaxf(fmaxf(v[0], v[1]), fmaxf(v[2], v[3]));
    #pragma unroll
    for (int o = 16; o > 0; o >>= 1) m = fmaxf(m, __shfl_xor_sync(0xffffffffu, m, o));
    float s = 0.f;
    #pragma unroll
    for (int i = 0; i < 4; i++) { v[i] = __expf(v[i] - m); s += v[i]; }
    #pragma unroll
    for (int o = 16; o > 0; o >>= 1) s += __shfl_xor_sync(0xffffffffu, s, o);
    float inv = 1.f / s;
    #pragma unroll
    for (int i = 0; i < 4; i++) {
        int q = lane + i * 32;
        S[base + q]  = to_tf32(v[i] * inv);
        Sc[base + q] = to_tf32(__expf(raw[i] + cadd - gm[b * Q + q]) * ginv[b * Q + q]);
    }
}

// ---------------- launch ----------------
extern "C" void kernel_launch(void* const* d_in, const int* in_sizes, int n_in,
                              void* d_out, int out_size) {
    const float* x_context    = (const float*)d_in[0];  // B,C,H
    const float* x_query      = (const float*)d_in[1];  // B,Q,H
    const float* context_mask = (const float*)d_in[2];  // B,C
    const float* query_mask   = (const float*)d_in[3];  // B,Q
    const float* W0           = (const float*)d_in[4];
    const float* W1           = (const float*)d_in[5];
    const float* W2           = (const float*)d_in[6];
    const float* bias         = (const float*)d_in[7];
    float* out = (float*)d_out;                          // [c2q | q2c], each B*C*H

    float *p_qw, *p_xqR, *p_xcR, *p_sub0, *p_sub1, *p_S, *p_Sc, *p_tmp,
          *p_pm, *p_ps, *p_gm, *p_ginv;
    cudaGetSymbolAddress((void**)&p_qw,   g_qw);
    cudaGetSymbolAddress((void**)&p_xqR,  g_xqR);
    cudaGetSymbolAddress((void**)&p_xcR,  g_xcR);
    cudaGetSymbolAddress((void**)&p_sub0, g_sub0);
    cudaGetSymbolAddress((void**)&p_sub1, g_sub1);
    cudaGetSymbolAddress((void**)&p_S,    g_S);
    cudaGetSymbolAddress((void**)&p_Sc,   g_Sc);
    cudaGetSymbolAddress((void**)&p_tmp,  g_tmp);
    cudaGetSymbolAddress((void**)&p_pm,   g_pm);
    cudaGetSymbolAddress((void**)&p_ps,   g_ps);
    cudaGetSymbolAddress((void**)&p_gm,   g_gm);
    cudaGetSymbolAddress((void**)&p_ginv, g_ginv);

    const size_t BCH = (size_t)B * C * H;

    // 1. prep (single launch; launch #1)
    prep_kernel<<<B * Q + B * C, 128>>>(x_query, x_context, W0, W1, W2,
                                        p_qw, p_xqR, p_xcR, p_sub0, p_sub1);

    // 2. S = tf32(Xc) @ tf32(qw)^T + sub1 + sub0 + bias   (launch #2)
    gemm_tf32_kernel<0, 0, 0><<<dim3(Q / 128, C / 128, B), 256>>>(
        p_xcR, p_qw, p_S, H, H, H, Q,
        (size_t)C * H, (size_t)Q * H, (size_t)C * Q,
        p_sub1, C, p_sub0, Q, bias);

    // 3. softmaxes (launches #3,#4,#5)
    softc_partial<<<dim3(NCH, B), Q>>>(p_S, context_mask, p_pm, p_ps);
    softc_combine<<<B, Q>>>(p_pm, p_ps, p_gm, p_ginv);
    fused_post<<<dim3(C / 8, B), 256>>>(p_S, p_Sc, context_mask, query_mask, p_gm, p_ginv);

    // 4. tmp = S_c^T @ Xc   (M=Q, N=H, K=C)   (launch #6 — ncu profiles this one)
    gemm_tf32_kernel<1, 1, 1><<<dim3(H / 128, Q / 128, B), 256>>>(
        p_Sc, p_xcR, p_tmp, C, Q, H, H,
        (size_t)C * Q, (size_t)C * H, (size_t)Q * H,
        nullptr, 0, nullptr, 0, nullptr);

    // 5. c2q = S_ @ Xq   (M=C, N=H, K=Q)
    gemm_tf32_kernel<0, 1, 0><<<dim3(H / 128, C / 128, B), 256>>>(
        p_S, p_xqR, out, Q, Q, H, H,
        (size_t)C * Q, (size_t)Q * H, (size_t)C * H,
        nullptr, 0, nullptr, 0, nullptr);

    // 6. q2c = S_ @ tmp  (M=C, N=H, K=Q)
    gemm_tf32_kernel<0, 1, 0><<<dim3(H / 128, C / 128, B), 256>>>(
        p_S, p_tmp, out + BCH, Q, Q, H, H,
        (size_t)C * Q, (size_t)Q * H, (size_t)C * H,
        nullptr, 0, nullptr, 0, nullptr);
}

// round 8
// speedup vs baseline: 3.3492x; 3.3492x over previous
#include <cuda_runtime.h>
#include <cuda_bf16.h>
#include <math.h>
#include <stdint.h>

#define NEG_INF_F (-1e30f)

static constexpr int B = 64;
static constexpr int C = 1024;
static constexpr int Q = 128;
static constexpr int H = 512;
static constexpr int NCH = 32;

// ---------------- scratch (device globals: allocation-free rule) ----------------
__device__ float g_qw[(size_t)B * Q * H];      // tf32(xq*W2)
__device__ float g_xqR[(size_t)B * Q * H];     // tf32(x_query)
__device__ float g_xcR[(size_t)B * C * H];     // tf32(x_context)
__device__ float g_sub0[B * Q];
__device__ float g_sub1[B * C];
__device__ float g_S[(size_t)B * C * Q];       // S, then tf32(S_) in place
__device__ float g_Sc[(size_t)B * C * Q];      // tf32(softmax over c)
__device__ float g_tmp[(size_t)B * Q * H];     // tf32(tmp)
__device__ float g_pm[B * NCH * Q];
__device__ float g_ps[B * NCH * Q];
__device__ float g_gm[B * Q];
__device__ float g_ginv[B * Q];

// ---------------- helpers ----------------
__device__ __forceinline__ float to_tf32(float x) {
    asm("cvt.rna.tf32.f32 %0, %1;" : "=f"(x) : "f"(x));
    return x;
}

__device__ __forceinline__ void mma_tf32(float* c, const unsigned* a, const unsigned* b) {
    asm volatile(
        "mma.sync.aligned.m16n8k8.row.col.f32.tf32.tf32.f32 "
        "{%0,%1,%2,%3}, {%4,%5,%6,%7}, {%8,%9}, {%0,%1,%2,%3};"
        : "+f"(c[0]), "+f"(c[1]), "+f"(c[2]), "+f"(c[3])
        : "r"(a[0]), "r"(a[1]), "r"(a[2]), "r"(a[3]), "r"(b[0]), "r"(b[1]));
}

__device__ __forceinline__ void cp16(unsigned s, const float* g) {
    asm volatile("cp.async.cg.shared.global [%0], [%1], 16;" :: "r"(s), "l"(g));
}
__device__ __forceinline__ void cp_commit() {
    asm volatile("cp.async.commit_group;" ::: "memory");
}
__device__ __forceinline__ void cp_wait2() {
    asm volatile("cp.async.wait_group 2;" ::: "memory");
}

__device__ __forceinline__ float block_reduce_sum_128(float v, float* red) {
    int t = threadIdx.x;
    #pragma unroll
    for (int o = 16; o > 0; o >>= 1) v += __shfl_xor_sync(0xffffffffu, v, o);
    if ((t & 31) == 0) red[t >> 5] = v;
    __syncthreads();
    return red[0] + red[1] + red[2] + red[3];
}

// ---------------- fused prep (one launch) ----------------
// blocks [0, B*Q): qw = tf32(xq*W2), xqR = tf32(xq), sub0 = dot(xq,W0)
// blocks [B*Q, B*Q + B*C): xcR = tf32(xc), sub1 = dot(xc,W1)
__global__ void prep_kernel(const float* __restrict__ xq, const float* __restrict__ xc,
                            const float* __restrict__ W0, const float* __restrict__ W1,
                            const float* __restrict__ W2,
                            float* __restrict__ qw, float* __restrict__ xqR,
                            float* __restrict__ xcR,
                            float* __restrict__ sub0, float* __restrict__ sub1) {
    int blk = blockIdx.x;
    int t = threadIdx.x;
    __shared__ float red[4];
    if (blk < B * Q) {
        const float* row = xq + (size_t)blk * H;
        float* o1 = qw + (size_t)blk * H;
        float* o2 = xqR + (size_t)blk * H;
        float s = 0.f;
        #pragma unroll
        for (int i = 0; i < H / 128; i++) {
            int h = i * 128 + t;
            float v = row[h];
            o1[h] = to_tf32(v * W2[h]);
            o2[h] = to_tf32(v);
            s = fmaf(v, W0[h], s);
        }
        s = block_reduce_sum_128(s, red);
        if (t == 0) sub0[blk] = s;
    } else {
        int bc = blk - B * Q;
        const float* row = xc + (size_t)bc * H;
        float* o = xcR + (size_t)bc * H;
        float s = 0.f;
        #pragma unroll
        for (int i = 0; i < H / 128; i++) {
            int h = i * 128 + t;
            float v = row[h];
            o[h] = to_tf32(v);
            s = fmaf(v, W1[h], s);
        }
        s = block_reduce_sum_128(s, red);
        if (t == 0) sub1[bc] = s;
    }
}

// ---------------- tf32 tensor-core GEMM: cp.async 4-stage pipeline (R5 structure) ----------------
// D[m,n] = sum_k A(m,k)*B(n,k)  (+rowBias[m] + colBias[n] + *scalarBias)
// Operands MUST be pre-rounded to tf32 (no cvt in the mainloop).
// AMODE 0: A row-major MxK (smem [r][16], swizzle k^(((r>>1)&3)<<2))
// AMODE 1: A row-major KxM (smem [k][128], swizzle m^((k&3)<<3))
// Same for B over N/K. Tile 128x128x16, 8 warps, warp tile 64x32.
template <int AMODE, int BMODE, int ROUND_OUT>
__global__ void __launch_bounds__(256)
gemm_tf32_kernel(const float* __restrict__ A, const float* __restrict__ Bp,
                 float* __restrict__ Cp, int K,
                 int lda, int ldb, int ldc,
                 size_t sA, size_t sB, size_t sC,
                 const float* __restrict__ rowBias, int rbStride,
                 const float* __restrict__ colBias, int cbStride,
                 const float* __restrict__ scalarBias) {
    extern __shared__ float smem[];
    float* As = smem;                 // 4 stages x 2048 floats
    float* Bs = smem + 4 * 2048;

    const int bz = blockIdx.z;
    A  += (size_t)bz * sA;
    Bp += (size_t)bz * sB;
    Cp += (size_t)bz * sC;
    const int tileM = blockIdx.y * 128;
    const int tileN = blockIdx.x * 128;
    const int tid = threadIdx.x;
    const int wid = tid >> 5, lane = tid & 31;
    const int warpM = (wid & 1) * 64;
    const int warpN = (wid >> 1) * 32;
    const int g = lane >> 2, tg = lane & 3;

    const unsigned asBase = (unsigned)__cvta_generic_to_shared(As);
    const unsigned bsBase = (unsigned)__cvta_generic_to_shared(Bs);

    unsigned aOff[2], bOff[2];
    const float* aG[2];
    const float* bG[2];
    const int aAdv = (AMODE == 0) ? 1 : lda;
    const int bAdv = (BMODE == 0) ? 1 : ldb;
    #pragma unroll
    for (int t = 0; t < 2; t++) {
        int c = tid + t * 256;
        if (AMODE == 0) {
            int r = c >> 2, kc = (c & 3) * 4;
            aOff[t] = r * 16 + (kc ^ ((((r >> 1) & 3)) << 2));
            aG[t] = A + (size_t)(tileM + r) * lda + kc;
        } else {
            int k = c >> 5, mc = (c & 31) * 4;
            aOff[t] = k * 128 + (mc ^ ((k & 3) << 3));
            aG[t] = A + (size_t)k * lda + tileM + mc;
        }
        if (BMODE == 0) {
            int r = c >> 2, kc = (c & 3) * 4;
            bOff[t] = r * 16 + (kc ^ ((((r >> 1) & 3)) << 2));
            bG[t] = Bp + (size_t)(tileN + r) * ldb + kc;
        } else {
            int k = c >> 5, nc = (c & 31) * 4;
            bOff[t] = k * 128 + (nc ^ ((k & 3) << 3));
            bG[t] = Bp + (size_t)k * ldb + tileN + nc;
        }
    }

    auto prefetch = [&](int it, int st) {
        int k0 = it << 4;
        #pragma unroll
        for (int t = 0; t < 2; t++) {
            cp16(asBase + (unsigned)(st * 2048 + aOff[t]) * 4, aG[t] + (size_t)k0 * aAdv);
            cp16(bsBase + (unsigned)(st * 2048 + bOff[t]) * 4, bG[t] + (size_t)k0 * bAdv);
        }
    };

    auto ldA = [&](int st, int m, int k) -> unsigned {
        int idx = (AMODE == 0) ? m * 16 + (k ^ ((((m >> 1) & 3)) << 2))
                               : k * 128 + (m ^ ((k & 3) << 3));
        return __float_as_uint(As[st * 2048 + idx]);
    };
    auto ldB = [&](int st, int n, int k) -> unsigned {
        int idx = (BMODE == 0) ? n * 16 + (k ^ ((((n >> 1) & 3)) << 2))
                               : k * 128 + (n ^ ((k & 3) << 3));
        return __float_as_uint(Bs[st * 2048 + idx]);
    };

    float acc[4][4][4] = {};
    const int nIter = K >> 4;

    prefetch(0, 0); cp_commit();
    prefetch(1, 1); cp_commit();

    for (int it = 0; it < nIter; it++) {
        const int st = it & 3;
        if (it + 2 < nIter) prefetch(it + 2, (it + 2) & 3);
        cp_commit();
        cp_wait2();
        __syncthreads();

        #pragma unroll
        for (int ks = 0; ks < 2; ks++) {
            const int kb = ks * 8;
            unsigned af[4][4], bf[4][2];
            #pragma unroll
            for (int mt = 0; mt < 4; mt++) {
                int m0 = warpM + mt * 16 + g;
                af[mt][0] = ldA(st, m0,     kb + tg);
                af[mt][1] = ldA(st, m0 + 8, kb + tg);
                af[mt][2] = ldA(st, m0,     kb + tg + 4);
                af[mt][3] = ldA(st, m0 + 8, kb + tg + 4);
            }
            #pragma unroll
            for (int nt = 0; nt < 4; nt++) {
                int n0 = warpN + nt * 8 + g;
                bf[nt][0] = ldB(st, n0, kb + tg);
                bf[nt][1] = ldB(st, n0, kb + tg + 4);
            }
            #pragma unroll
            for (int mt = 0; mt < 4; mt++)
                #pragma unroll
                for (int nt = 0; nt < 4; nt++)
                    mma_tf32(acc[mt][nt], af[mt], bf[nt]);
        }
    }

    // ---- epilogue ----
    const float sb = scalarBias ? __ldg(scalarBias) : 0.f;
    #pragma unroll
    for (int mt = 0; mt < 4; mt++) {
        int r0 = tileM + warpM + mt * 16 + g;
        int r1 = r0 + 8;
        float rb0 = rowBias ? rowBias[bz * rbStride + r0] + sb : sb;
        float rb1 = rowBias ? rowBias[bz * rbStride + r1] + sb : sb;
        #pragma unroll
        for (int nt = 0; nt < 4; nt++) {
            int c0 = tileN + warpN + nt * 8 + tg * 2;
            float cb0 = colBias ? colBias[bz * cbStride + c0    ] : 0.f;
            float cb1 = colBias ? colBias[bz * cbStride + c0 + 1] : 0.f;
            float w0 = acc[mt][nt][0] + rb0 + cb0;
            float w1 = acc[mt][nt][1] + rb0 + cb1;
            float w2 = acc[mt][nt][2] + rb1 + cb0;
            float w3 = acc[mt][nt][3] + rb1 + cb1;
            if (ROUND_OUT) { w0 = to_tf32(w0); w1 = to_tf32(w1); w2 = to_tf32(w2); w3 = to_tf32(w3); }
            Cp[(size_t)r0 * ldc + c0    ] = w0;
            Cp[(size_t)r0 * ldc + c0 + 1] = w1;
            Cp[(size_t)r1 * ldc + c0    ] = w2;
            Cp[(size_t)r1 * ldc + c0 + 1] = w3;
        }
    }
}

// ---------------- softmax over c (axis=1): partial + combine ----------------
__global__ void softc_partial(const float* __restrict__ S,
                              const float* __restrict__ cmask,
                              float* __restrict__ pm, float* __restrict__ ps) {
    int chunk = blockIdx.x, b = blockIdx.y;
    int q = threadIdx.x;
    constexpr int RB = C / NCH;
    const float* Sb = S + ((size_t)b * C + chunk * RB) * Q + q;
    const float* mcb = cmask + (size_t)b * C + chunk * RB;
    float m = -INFINITY, s = 0.f;
    #pragma unroll 4
    for (int c = 0; c < RB; c++) {
        float v = Sb[(size_t)c * Q] + (1.f - mcb[c]) * NEG_INF_F;
        float mn = fmaxf(m, v);
        s = s * __expf(m - mn) + __expf(v - mn);
        m = mn;
    }
    pm[(b * NCH + chunk) * Q + q] = m;
    ps[(b * NCH + chunk) * Q + q] = s;
}

__global__ void softc_combine(const float* __restrict__ pm,
                              const float* __restrict__ ps,
                              float* __restrict__ gm, float* __restrict__ ginv) {
    int b = blockIdx.x, q = threadIdx.x;
    float m = -INFINITY;
    #pragma unroll
    for (int ch = 0; ch < NCH; ch++)
        m = fmaxf(m, pm[(b * NCH + ch) * Q + q]);
    float s = 0.f;
    #pragma unroll
    for (int ch = 0; ch < NCH; ch++)
        s += ps[(b * NCH + ch) * Q + q] * __expf(pm[(b * NCH + ch) * Q + q] - m);
    gm[b * Q + q] = m;
    ginv[b * Q + q] = 1.f / s;
}

// ---------------- fused: softmax_q (in place, tf32) + softc write (Sc, tf32) ----------------
__global__ void fused_post(float* __restrict__ S,
                           float* __restrict__ Sc,
                           const float* __restrict__ cmask,
                           const float* __restrict__ qmask,
                           const float* __restrict__ gm,
                           const float* __restrict__ ginv) {
    int b = blockIdx.y;
    int c = blockIdx.x * 8 + (threadIdx.x >> 5);
    int lane = threadIdx.x & 31;
    size_t base = ((size_t)b * C + c) * Q;
    float cadd = (1.f - cmask[b * C + c]) * NEG_INF_F;

    float raw[4], v[4];
    #pragma unroll
    for (int i = 0; i < 4; i++) {
        int q = lane + i * 32;
        raw[i] = S[base + q];
        v[i] = raw[i] + (1.f - qmask[b * Q + q]) * NEG_INF_F;
    }
    float m = fmaxf(fmaxf(v[0], v[1]), fmaxf(v[2], v[3]));
    #pragma unroll
    for (int o = 16; o > 0; o >>= 1) m = fmaxf(m, __shfl_xor_sync(0xffffffffu, m, o));
    float s = 0.f;
    #pragma unroll
    for (int i = 0; i < 4; i++) { v[i] = __expf(v[i] - m); s += v[i]; }
    #pragma unroll
    for (int o = 16; o > 0; o >>= 1) s += __shfl_xor_sync(0xffffffffu, s, o);
    float inv = 1.f / s;
    #pragma unroll
    for (int i = 0; i < 4; i++) {
        int q = lane + i * 32;
        S[base + q]  = to_tf32(v[i] * inv);
        Sc[base + q] = to_tf32(__expf(raw[i] + cadd - gm[b * Q + q]) * ginv[b * Q + q]);
    }
}

// ---------------- launch ----------------
extern "C" void kernel_launch(void* const* d_in, const int* in_sizes, int n_in,
                              void* d_out, int out_size) {
    const float* x_context    = (const float*)d_in[0];  // B,C,H
    const float* x_query      = (const float*)d_in[1];  // B,Q,H
    const float* context_mask = (const float*)d_in[2];  // B,C
    const float* query_mask   = (const float*)d_in[3];  // B,Q
    const float* W0           = (const float*)d_in[4];
    const float* W1           = (const float*)d_in[5];
    const float* W2           = (const float*)d_in[6];
    const float* bias         = (const float*)d_in[7];
    float* out = (float*)d_out;                          // [c2q | q2c], each B*C*H

    float *p_qw, *p_xqR, *p_xcR, *p_sub0, *p_sub1, *p_S, *p_Sc, *p_tmp,
          *p_pm, *p_ps, *p_gm, *p_ginv;
    cudaGetSymbolAddress((void**)&p_qw,   g_qw);
    cudaGetSymbolAddress((void**)&p_xqR,  g_xqR);
    cudaGetSymbolAddress((void**)&p_xcR,  g_xcR);
    cudaGetSymbolAddress((void**)&p_sub0, g_sub0);
    cudaGetSymbolAddress((void**)&p_sub1, g_sub1);
    cudaGetSymbolAddress((void**)&p_S,    g_S);
    cudaGetSymbolAddress((void**)&p_Sc,   g_Sc);
    cudaGetSymbolAddress((void**)&p_tmp,  g_tmp);
    cudaGetSymbolAddress((void**)&p_pm,   g_pm);
    cudaGetSymbolAddress((void**)&p_ps,   g_ps);
    cudaGetSymbolAddress((void**)&p_gm,   g_gm);
    cudaGetSymbolAddress((void**)&p_ginv, g_ginv);

    const size_t BCH = (size_t)B * C * H;
    const int SMEM = 4 * 2048 * 2 * sizeof(float);   // 64 KB

    cudaFuncSetAttribute(gemm_tf32_kernel<0, 0, 0>, cudaFuncAttributeMaxDynamicSharedMemorySize, SMEM);
    cudaFuncSetAttribute(gemm_tf32_kernel<1, 1, 1>, cudaFuncAttributeMaxDynamicSharedMemorySize, SMEM);
    cudaFuncSetAttribute(gemm_tf32_kernel<0, 1, 0>, cudaFuncAttributeMaxDynamicSharedMemorySize, SMEM);

    // 1. prep (single launch)
    prep_kernel<<<B * Q + B * C, 128>>>(x_query, x_context, W0, W1, W2,
                                        p_qw, p_xqR, p_xcR, p_sub0, p_sub1);

    // 2. S = tf32(Xc) @ tf32(qw)^T + sub1 + sub0 + bias
    gemm_tf32_kernel<0, 0, 0><<<dim3(Q / 128, C / 128, B), 256, SMEM>>>(
        p_xcR, p_qw, p_S, H, H, H, Q,
        (size_t)C * H, (size_t)Q * H, (size_t)C * Q,
        p_sub1, C, p_sub0, Q, bias);

    // 3. softmaxes
    softc_partial<<<dim3(NCH, B), Q>>>(p_S, context_mask, p_pm, p_ps);
    softc_combine<<<B, Q>>>(p_pm, p_ps, p_gm, p_ginv);
    fused_post<<<dim3(C / 8, B), 256>>>(p_S, p_Sc, context_mask, query_mask, p_gm, p_ginv);

    // 4. tmp = S_c^T @ Xc   (M=Q, N=H, K=C), output tf32-rounded
    gemm_tf32_kernel<1, 1, 1><<<dim3(H / 128, Q / 128, B), 256, SMEM>>>(
        p_Sc, p_xcR, p_tmp, C, Q, H, H,
        (size_t)C * Q, (size_t)C * H, (size_t)Q * H,
        nullptr, 0, nullptr, 0, nullptr);

    // 5. c2q = S_ @ Xq   (M=C, N=H, K=Q)
    gemm_tf32_kernel<0, 1, 0><<<dim3(H / 128, C / 128, B), 256, SMEM>>>(
        p_S, p_xqR, out, Q, Q, H, H,
        (size_t)C * Q, (size_t)Q * H, (size_t)C * H,
        nullptr, 0, nullptr, 0, nullptr);

    // 6. q2c = S_ @ tmp  (M=C, N=H, K=Q)
    gemm_tf32_kernel<0, 1, 0><<<dim3(H / 128, C / 128, B), 256, SMEM>>>(
        p_S, p_tmp, out + BCH, Q, Q, H, H,
        (size_t)C * Q, (size_t)Q * H, (size_t)C * H,
        nullptr, 0, nullptr, 0, nullptr);
}

// round 9
// speedup vs baseline: 4.0975x; 1.2234x over previous
#include <cuda_runtime.h>
#include <cuda_fp16.h>
#include <math.h>
#include <stdint.h>

#define NEG_INF_F (-1e30f)

static constexpr int B = 64;
static constexpr int C = 1024;
static constexpr int Q = 128;
static constexpr int H = 512;
static constexpr int NCH = 32;

// ---------------- scratch (device globals: allocation-free rule) ----------------
__device__ __align__(256) __half g_qwH[(size_t)B * Q * H];   // half(xq*W2)  [B,Q,H]
__device__ __align__(256) __half g_xcH[(size_t)B * C * H];   // half(xc)     [B,C,H]
__device__ __align__(256) __half g_xcT[(size_t)B * H * C];   // half(xc^T)   [B,H,C]
__device__ __align__(256) __half g_xqT[(size_t)B * H * Q];   // half(xq^T)   [B,H,Q]
__device__ __align__(256) __half g_Sh[(size_t)B * C * Q];    // half(softmax_q(S)) [B,C,Q]
__device__ __align__(256) __half g_ScT[(size_t)B * Q * C];   // half(softmax_c(S))^T [B,Q,C]
__device__ __align__(256) __half g_tmpT[(size_t)B * H * Q];  // half(tmp^T)  [B,H,Q]
__device__ float g_S[(size_t)B * C * Q];                     // fp32 raw S
__device__ float g_tmp[(size_t)B * Q * H];                   // fp32 tmp [B,Q,H]
__device__ float g_sub0[B * Q];
__device__ float g_sub1[B * C];
__device__ float g_pm[B * NCH * Q];
__device__ float g_ps[B * NCH * Q];
__device__ float g_gm[B * Q];
__device__ float g_ginv[B * Q];

// ---------------- helpers ----------------
__device__ __forceinline__ void mma_f16(float* c, const unsigned* a, const unsigned* b) {
    asm volatile(
        "mma.sync.aligned.m16n8k16.row.col.f32.f16.f16.f32 "
        "{%0,%1,%2,%3}, {%4,%5,%6,%7}, {%8,%9}, {%0,%1,%2,%3};"
        : "+f"(c[0]), "+f"(c[1]), "+f"(c[2]), "+f"(c[3])
        : "r"(a[0]), "r"(a[1]), "r"(a[2]), "r"(a[3]), "r"(b[0]), "r"(b[1]));
}

__device__ __forceinline__ void cp16(unsigned s, const void* g) {
    asm volatile("cp.async.cg.shared.global [%0], [%1], 16;" :: "r"(s), "l"(g));
}
__device__ __forceinline__ void cp_commit() {
    asm volatile("cp.async.commit_group;" ::: "memory");
}
__device__ __forceinline__ void cp_wait2() {
    asm volatile("cp.async.wait_group 2;" ::: "memory");
}

__device__ __forceinline__ float block_reduce_sum_128(float v, float* red) {
    int t = threadIdx.x;
    #pragma unroll
    for (int o = 16; o > 0; o >>= 1) v += __shfl_xor_sync(0xffffffffu, v, o);
    if ((t & 31) == 0) red[t >> 5] = v;
    __syncthreads();
    return red[0] + red[1] + red[2] + red[3];
}

// ---------------- fused prep ----------------
// blocks [0, B*Q): qwH = half(xq*W2), sub0 = dot(xq,W0)
// blocks [B*Q, B*Q+B*C): xcH = half(xc), sub1 = dot(xc,W1)
__global__ void prep_kernel(const float* __restrict__ xq, const float* __restrict__ xc,
                            const float* __restrict__ W0, const float* __restrict__ W1,
                            const float* __restrict__ W2,
                            __half* __restrict__ qwH, __half* __restrict__ xcH,
                            float* __restrict__ sub0, float* __restrict__ sub1) {
    int blk = blockIdx.x;
    int t = threadIdx.x;
    __shared__ float red[4];
    if (blk < B * Q) {
        const float* row = xq + (size_t)blk * H;
        __half* o1 = qwH + (size_t)blk * H;
        float s = 0.f;
        #pragma unroll
        for (int i = 0; i < H / 128; i++) {
            int h = i * 128 + t;
            float v = row[h];
            o1[h] = __float2half(v * W2[h]);
            s = fmaf(v, W0[h], s);
        }
        s = block_reduce_sum_128(s, red);
        if (t == 0) sub0[blk] = s;
    } else {
        int bc = blk - B * Q;
        const float* row = xc + (size_t)bc * H;
        __half* o = xcH + (size_t)bc * H;
        float s = 0.f;
        #pragma unroll
        for (int i = 0; i < H / 128; i++) {
            int h = i * 128 + t;
            float v = row[h];
            o[h] = __float2half(v);
            s = fmaf(v, W1[h], s);
        }
        s = block_reduce_sum_128(s, red);
        if (t == 0) sub1[bc] = s;
    }
}

// ---------------- transpose: in fp32 [R,Cc] -> out half [Cc,R], per batch ----------------
__global__ void transpose_h(const float* __restrict__ in, __half* __restrict__ out,
                            int R, int Cc) {
    __shared__ float tile[32][33];
    in  += (size_t)blockIdx.z * R * Cc;
    out += (size_t)blockIdx.z * R * Cc;
    int c0 = blockIdx.x * 32, r0 = blockIdx.y * 32;
    int x = threadIdx.x, y = threadIdx.y;
    #pragma unroll
    for (int j = 0; j < 4; j++)
        tile[y + j * 8][x] = in[(size_t)(r0 + y + j * 8) * Cc + c0 + x];
    __syncthreads();
    #pragma unroll
    for (int j = 0; j < 4; j++)
        out[(size_t)(c0 + y + j * 8) * R + r0 + x] = __float2half(tile[x][y + j * 8]);
}

// ---------------- fp16 tensor-core GEMM: cp.async 4-stage pipeline ----------------
// D[m,n] = sum_k A[m,k]*B[n,k]; A half MxK row-major (lda), B half NxK row-major (ldb).
// Tile 128x128x16, 8 warps, warp tile 64x32, m16n8k16 MMAs.
// Smem: rows of 16 halves (32B = two 16B chunks); chunk swizzle: phys = ch ^ ((r>>2)&1).
__global__ void __launch_bounds__(256)
gemm_f16(const __half* __restrict__ A, const __half* __restrict__ Bp,
         float* __restrict__ Cp, int K,
         int lda, int ldb, int ldc,
         size_t sA, size_t sB, size_t sC,
         const float* __restrict__ rowBias, int rbStride,
         const float* __restrict__ colBias, int cbStride,
         const float* __restrict__ scalarBias) {
    __shared__ __half As[4][128 * 16];   // 4 stages x 4KB
    __shared__ __half Bs[4][128 * 16];

    const int bz = blockIdx.z;
    A  += (size_t)bz * sA;
    Bp += (size_t)bz * sB;
    Cp += (size_t)bz * sC;
    const int tileM = blockIdx.y * 128;
    const int tileN = blockIdx.x * 128;
    const int tid = threadIdx.x;
    const int wid = tid >> 5, lane = tid & 31;
    const int warpM = (wid & 1) * 64;
    const int warpN = (wid >> 1) * 32;
    const int g = lane >> 2, tg = lane & 3;

    const unsigned asB = (unsigned)__cvta_generic_to_shared(As);
    const unsigned bsB = (unsigned)__cvta_generic_to_shared(Bs);
    const char* asP = (const char*)As;
    const char* bsP = (const char*)Bs;

    // staging: 256 chunks (16B) per operand per iter; thread -> (row, chunk)
    const int r = tid >> 1, ch = tid & 1;
    const unsigned stOff = (unsigned)(r * 32 + ((ch ^ ((r >> 2) & 1)) * 16));
    const __half* aG = A + (size_t)(tileM + r) * lda + ch * 8;
    const __half* bG = Bp + (size_t)(tileN + r) * ldb + ch * 8;

    auto prefetch = [&](int it, int st) {
        int k0 = it << 4;
        cp16(asB + st * 4096 + stOff, aG + k0);
        cp16(bsB + st * 4096 + stOff, bG + k0);
    };
    auto ldA2 = [&](int st, int m, int k) -> unsigned {   // b32 = halves (m,k),(m,k+1)
        int off = m * 32 + 2 * (k ^ (((m >> 2) & 1) << 3));
        return *(const unsigned*)(asP + st * 4096 + off);
    };
    auto ldB2 = [&](int st, int n, int k) -> unsigned {
        int off = n * 32 + 2 * (k ^ (((n >> 2) & 1) << 3));
        return *(const unsigned*)(bsP + st * 4096 + off);
    };

    float acc[4][4][4] = {};
    const int nIter = K >> 4;

    prefetch(0, 0); cp_commit();
    prefetch(1, 1); cp_commit();

    for (int it = 0; it < nIter; it++) {
        const int st = it & 3;
        if (it + 2 < nIter) prefetch(it + 2, (it + 2) & 3);
        cp_commit();
        cp_wait2();
        __syncthreads();

        unsigned af[4][4], bf[4][2];
        #pragma unroll
        for (int mt = 0; mt < 4; mt++) {
            int m0 = warpM + mt * 16 + g;
            af[mt][0] = ldA2(st, m0,     2 * tg);
            af[mt][1] = ldA2(st, m0 + 8, 2 * tg);
            af[mt][2] = ldA2(st, m0,     2 * tg + 8);
            af[mt][3] = ldA2(st, m0 + 8, 2 * tg + 8);
        }
        #pragma unroll
        for (int nt = 0; nt < 4; nt++) {
            int n0 = warpN + nt * 8 + g;
            bf[nt][0] = ldB2(st, n0, 2 * tg);
            bf[nt][1] = ldB2(st, n0, 2 * tg + 8);
        }
        #pragma unroll
        for (int mt = 0; mt < 4; mt++)
            #pragma unroll
            for (int nt = 0; nt < 4; nt++)
                mma_f16(acc[mt][nt], af[mt], bf[nt]);
    }

    // ---- epilogue ----
    const float sb = scalarBias ? __ldg(scalarBias) : 0.f;
    #pragma unroll
    for (int mt = 0; mt < 4; mt++) {
        int r0 = tileM + warpM + mt * 16 + g;
        int r1 = r0 + 8;
        float rb0 = rowBias ? rowBias[bz * rbStride + r0] + sb : sb;
        float rb1 = rowBias ? rowBias[bz * rbStride + r1] + sb : sb;
        #pragma unroll
        for (int nt = 0; nt < 4; nt++) {
            int c0 = tileN + warpN + nt * 8 + tg * 2;
            float cb0 = colBias ? colBias[bz * cbStride + c0    ] : 0.f;
            float cb1 = colBias ? colBias[bz * cbStride + c0 + 1] : 0.f;
            Cp[(size_t)r0 * ldc + c0    ] = acc[mt][nt][0] + rb0 + cb0;
            Cp[(size_t)r0 * ldc + c0 + 1] = acc[mt][nt][1] + rb0 + cb1;
            Cp[(size_t)r1 * ldc + c0    ] = acc[mt][nt][2] + rb1 + cb0;
            Cp[(size_t)r1 * ldc + c0 + 1] = acc[mt][nt][3] + rb1 + cb1;
        }
    }
}

// ---------------- softmax over c (axis=1): partial + combine (fp32 S) ----------------
__global__ void softc_partial(const float* __restrict__ S,
                              const float* __restrict__ cmask,
                              float* __restrict__ pm, float* __restrict__ ps) {
    int chunk = blockIdx.x, b = blockIdx.y;
    int q = threadIdx.x;
    constexpr int RB = C / NCH;
    const float* Sb = S + ((size_t)b * C + chunk * RB) * Q + q;
    const float* mcb = cmask + (size_t)b * C + chunk * RB;
    float m = -INFINITY, s = 0.f;
    #pragma unroll 4
    for (int c = 0; c < RB; c++) {
        float v = Sb[(size_t)c * Q] + (1.f - mcb[c]) * NEG_INF_F;
        float mn = fmaxf(m, v);
        s = s * __expf(m - mn) + __expf(v - mn);
        m = mn;
    }
    pm[(b * NCH + chunk) * Q + q] = m;
    ps[(b * NCH + chunk) * Q + q] = s;
}

__global__ void softc_combine(const float* __restrict__ pm,
                              const float* __restrict__ ps,
                              float* __restrict__ gm, float* __restrict__ ginv) {
    int b = blockIdx.x, q = threadIdx.x;
    float m = -INFINITY;
    #pragma unroll
    for (int ch = 0; ch < NCH; ch++)
        m = fmaxf(m, pm[(b * NCH + ch) * Q + q]);
    float s = 0.f;
    #pragma unroll
    for (int ch = 0; ch < NCH; ch++)
        s += ps[(b * NCH + ch) * Q + q] * __expf(pm[(b * NCH + ch) * Q + q] - m);
    gm[b * Q + q] = m;
    ginv[b * Q + q] = 1.f / s;
}

// ---------------- fused post: softmax_q -> Sh [C,Q] half; softc -> ScT [Q,C] half ----------------
// 512 threads: warp per c, 16 c per block; ScT written via smem-staged transpose.
__global__ void fused_post(const float* __restrict__ S,
                           __half* __restrict__ Sh, __half* __restrict__ ScT,
                           const float* __restrict__ cmask,
                           const float* __restrict__ qmask,
                           const float* __restrict__ gm,
                           const float* __restrict__ ginv) {
    __shared__ __half stg[128][20];    // [q][c-within-block], pitch 20 (8B-aligned groups)
    int b = blockIdx.y;
    int cBase = blockIdx.x * 16;
    int wid = threadIdx.x >> 5, lane = threadIdx.x & 31;
    int c = cBase + wid;
    size_t base = ((size_t)b * C + c) * Q;
    float cadd = (1.f - cmask[b * C + c]) * NEG_INF_F;

    float raw[4], v[4];
    #pragma unroll
    for (int i = 0; i < 4; i++) {
        int q = lane + i * 32;
        raw[i] = S[base + q];
        v[i] = raw[i] + (1.f - qmask[b * Q + q]) * NEG_INF_F;
    }
    float m = fmaxf(fmaxf(v[0], v[1]), fmaxf(v[2], v[3]));
    #pragma unroll
    for (int o = 16; o > 0; o >>= 1) m = fmaxf(m, __shfl_xor_sync(0xffffffffu, m, o));
    float s = 0.f;
    #pragma unroll
    for (int i = 0; i < 4; i++) { v[i] = __expf(v[i] - m); s += v[i]; }
    #pragma unroll
    for (int o = 16; o > 0; o >>= 1) s += __shfl_xor_sync(0xffffffffu, s, o);
    float inv = 1.f / s;
    #pragma unroll
    for (int i = 0; i < 4; i++) {
        int q = lane + i * 32;
        Sh[base + q] = __float2half(v[i] * inv);
        stg[q][wid] = __float2half(__expf(raw[i] + cadd - gm[b * Q + q]) * ginv[b * Q + q]);
    }
    __syncthreads();
    // write ScT: 512 threads, each 4 halves (8B); 4 threads cover one q-row (16 halves)
    int t = threadIdx.x;
    int q = t >> 2, part = t & 3;
    uint2 val = *(const uint2*)&stg[q][part * 4];
    *(uint2*)&ScT[((size_t)b * Q + q) * C + cBase + part * 4] = val;
}

// ---------------- launch ----------------
extern "C" void kernel_launch(void* const* d_in, const int* in_sizes, int n_in,
                              void* d_out, int out_size) {
    const float* x_context    = (const float*)d_in[0];  // B,C,H
    const float* x_query      = (const float*)d_in[1];  // B,Q,H
    const float* context_mask = (const float*)d_in[2];  // B,C
    const float* query_mask   = (const float*)d_in[3];  // B,Q
    const float* W0           = (const float*)d_in[4];
    const float* W1           = (const float*)d_in[5];
    const float* W2           = (const float*)d_in[6];
    const float* bias         = (const float*)d_in[7];
    float* out = (float*)d_out;                          // [c2q | q2c], each B*C*H

    __half *p_qwH, *p_xcH, *p_xcT, *p_xqT, *p_Sh, *p_ScT, *p_tmpT;
    float *p_S, *p_tmp, *p_sub0, *p_sub1, *p_pm, *p_ps, *p_gm, *p_ginv;
    cudaGetSymbolAddress((void**)&p_qwH,  g_qwH);
    cudaGetSymbolAddress((void**)&p_xcH,  g_xcH);
    cudaGetSymbolAddress((void**)&p_xcT,  g_xcT);
    cudaGetSymbolAddress((void**)&p_xqT,  g_xqT);
    cudaGetSymbolAddress((void**)&p_Sh,   g_Sh);
    cudaGetSymbolAddress((void**)&p_ScT,  g_ScT);
    cudaGetSymbolAddress((void**)&p_tmpT, g_tmpT);
    cudaGetSymbolAddress((void**)&p_S,    g_S);
    cudaGetSymbolAddress((void**)&p_tmp,  g_tmp);
    cudaGetSymbolAddress((void**)&p_sub0, g_sub0);
    cudaGetSymbolAddress((void**)&p_sub1, g_sub1);
    cudaGetSymbolAddress((void**)&p_pm,   g_pm);
    cudaGetSymbolAddress((void**)&p_ps,   g_ps);
    cudaGetSymbolAddress((void**)&p_gm,   g_gm);
    cudaGetSymbolAddress((void**)&p_ginv, g_ginv);

    const size_t BCH = (size_t)B * C * H;

    // 1. prep + layout transposes
    prep_kernel<<<B * Q + B * C, 128>>>(x_query, x_context, W0, W1, W2,
                                        p_qwH, p_xcH, p_sub0, p_sub1);
    transpose_h<<<dim3(H / 32, Q / 32, B), dim3(32, 8)>>>(x_query, p_xqT, Q, H);
    transpose_h<<<dim3(H / 32, C / 32, B), dim3(32, 8)>>>(x_context, p_xcT, C, H);

    // 2. S = xcH @ qwH^T + sub1 + sub0 + bias   (M=C, N=Q, K=H)
    gemm_f16<<<dim3(Q / 128, C / 128, B), 256>>>(
        p_xcH, p_qwH, p_S, H, H, H, Q,
        (size_t)C * H, (size_t)Q * H, (size_t)C * Q,
        p_sub1, C, p_sub0, Q, bias);

    // 3. softmaxes
    softc_partial<<<dim3(NCH, B), Q>>>(p_S, context_mask, p_pm, p_ps);
    softc_combine<<<B, Q>>>(p_pm, p_ps, p_gm, p_ginv);
    fused_post<<<dim3(C / 16, B), 512>>>(p_S, p_Sh, p_ScT, context_mask, query_mask,
                                         p_gm, p_ginv);

    // 4. tmp = Sc^T @ Xc   (M=Q, N=H, K=C): A=ScT [Q,C], B=xcT [H,C]
    gemm_f16<<<dim3(H / 128, Q / 128, B), 256>>>(
        p_ScT, p_xcT, p_tmp, C, C, C, H,
        (size_t)Q * C, (size_t)H * C, (size_t)Q * H,
        nullptr, 0, nullptr, 0, nullptr);
    transpose_h<<<dim3(H / 32, Q / 32, B), dim3(32, 8)>>>(p_tmp, p_tmpT, Q, H);

    // 5. c2q = S_ @ Xq   (M=C, N=H, K=Q): A=Sh [C,Q], B=xqT [H,Q]
    gemm_f16<<<dim3(H / 128, C / 128, B), 256>>>(
        p_Sh, p_xqT, out, Q, Q, Q, H,
        (size_t)C * Q, (size_t)H * Q, (size_t)C * H,
        nullptr, 0, nullptr, 0, nullptr);

    // 6. q2c = S_ @ tmp  (M=C, N=H, K=Q): A=Sh [C,Q], B=tmpT [H,Q]
    gemm_f16<<<dim3(H / 128, C / 128, B), 256>>>(
        p_Sh, p_tmpT, out + BCH, Q, Q, Q, H,
        (size_t)C * Q, (size_t)H * Q, (size_t)C * H,
        nullptr, 0, nullptr, 0, nullptr);
}

// round 14
// speedup vs baseline: 4.7047x; 1.1482x over previous
#include <cuda_runtime.h>
#include <cuda_fp16.h>
#include <math.h>
#include <stdint.h>

#define NEG_INF_F (-1e30f)

static constexpr int B = 64;
static constexpr int C = 1024;
static constexpr int Q = 128;
static constexpr int H = 512;
static constexpr int NCH = 32;

// ---------------- scratch (device globals: allocation-free rule) ----------------
__device__ __align__(256) __half g_qwH[(size_t)B * Q * H];   // half(xq*W2)  [B,Q,H]
__device__ __align__(256) __half g_xcH[(size_t)B * C * H];   // half(xc)     [B,C,H]
__device__ __align__(256) __half g_xcT[(size_t)B * H * C];   // half(xc^T)   [B,H,C]
__device__ __align__(256) __half g_xqT[(size_t)B * H * Q];   // half(xq^T)   [B,H,Q]
__device__ __align__(256) __half g_Sh[(size_t)B * C * Q];    // half(softmax_q(S)) [B,C,Q]
__device__ __align__(256) __half g_ScT[(size_t)B * Q * C];   // half(softmax_c(S))^T [B,Q,C]
__device__ __align__(256) __half g_tmpT[(size_t)B * H * Q];  // half(tmp^T)  [B,H,Q]
__device__ float g_S[(size_t)B * C * Q];                     // fp32 raw S
__device__ float g_tmp[(size_t)B * Q * H];                   // fp32 tmp [B,Q,H]
__device__ float g_sub0[B * Q];
__device__ float g_sub1[B * C];
__device__ float g_pm[B * NCH * Q];
__device__ float g_ps[B * NCH * Q];
__device__ float g_gm[B * Q];
__device__ float g_ginv[B * Q];

// ---------------- helpers ----------------
__device__ __forceinline__ void mma_f16(float* c, const unsigned* a, const unsigned* b) {
    asm volatile(
        "mma.sync.aligned.m16n8k16.row.col.f32.f16.f16.f32 "
        "{%0,%1,%2,%3}, {%4,%5,%6,%7}, {%8,%9}, {%0,%1,%2,%3};"
        : "+f"(c[0]), "+f"(c[1]), "+f"(c[2]), "+f"(c[3])
        : "r"(a[0]), "r"(a[1]), "r"(a[2]), "r"(a[3]), "r"(b[0]), "r"(b[1]));
}

__device__ __forceinline__ void ldsm4(unsigned* r, unsigned addr) {
    asm volatile("ldmatrix.sync.aligned.m8n8.x4.shared.b16 {%0,%1,%2,%3}, [%4];"
                 : "=r"(r[0]), "=r"(r[1]), "=r"(r[2]), "=r"(r[3]) : "r"(addr));
}

__device__ __forceinline__ void cp16(unsigned s, const void* g) {
    asm volatile("cp.async.cg.shared.global [%0], [%1], 16;" :: "r"(s), "l"(g));
}
__device__ __forceinline__ void cp_commit() {
    asm volatile("cp.async.commit_group;" ::: "memory");
}
__device__ __forceinline__ void cp_wait2() {
    asm volatile("cp.async.wait_group 2;" ::: "memory");
}

__device__ __forceinline__ float block_reduce_sum_128(float v, float* red) {
    int t = threadIdx.x;
    #pragma unroll
    for (int o = 16; o > 0; o >>= 1) v += __shfl_xor_sync(0xffffffffu, v, o);
    if ((t & 31) == 0) red[t >> 5] = v;
    __syncthreads();
    return red[0] + red[1] + red[2] + red[3];
}

// ---------------- fused prep ----------------
__global__ void prep_kernel(const float* __restrict__ xq, const float* __restrict__ xc,
                            const float* __restrict__ W0, const float* __restrict__ W1,
                            const float* __restrict__ W2,
                            __half* __restrict__ qwH, __half* __restrict__ xcH,
                            float* __restrict__ sub0, float* __restrict__ sub1) {
    int blk = blockIdx.x;
    int t = threadIdx.x;
    __shared__ float red[4];
    if (blk < B * Q) {
        const float* row = xq + (size_t)blk * H;
        __half* o1 = qwH + (size_t)blk * H;
        float s = 0.f;
        #pragma unroll
        for (int i = 0; i < H / 128; i++) {
            int h = i * 128 + t;
            float v = row[h];
            o1[h] = __float2half(v * W2[h]);
            s = fmaf(v, W0[h], s);
        }
        s = block_reduce_sum_128(s, red);
        if (t == 0) sub0[blk] = s;
    } else {
        int bc = blk - B * Q;
        const float* row = xc + (size_t)bc * H;
        __half* o = xcH + (size_t)bc * H;
        float s = 0.f;
        #pragma unroll
        for (int i = 0; i < H / 128; i++) {
            int h = i * 128 + t;
            float v = row[h];
            o[h] = __float2half(v);
            s = fmaf(v, W1[h], s);
        }
        s = block_reduce_sum_128(s, red);
        if (t == 0) sub1[bc] = s;
    }
}

// ---------------- transpose: in fp32 [R,Cc] -> out half [Cc,R], per batch ----------------
__global__ void transpose_h(const float* __restrict__ in, __half* __restrict__ out,
                            int R, int Cc) {
    __shared__ float tile[32][33];
    in  += (size_t)blockIdx.z * R * Cc;
    out += (size_t)blockIdx.z * R * Cc;
    int c0 = blockIdx.x * 32, r0 = blockIdx.y * 32;
    int x = threadIdx.x, y = threadIdx.y;
    #pragma unroll
    for (int j = 0; j < 4; j++)
        tile[y + j * 8][x] = in[(size_t)(r0 + y + j * 8) * Cc + c0 + x];
    __syncthreads();
    #pragma unroll
    for (int j = 0; j < 4; j++)
        out[(size_t)(c0 + y + j * 8) * R + r0 + x] = __float2half(tile[x][y + j * 8]);
}

// ---------------- fp16 tensor-core GEMM: cp.async 4-stage, BK=32, ldmatrix ----------------
// D[m,n] = sum_k A[m,k]*B[n,k]; A half MxK row-major (lda), B half NxK row-major (ldb).
// Tile 128x128x32 per stage, 8 warps, warp tile 64x32, m16n8k16 MMAs (2 k-steps/stage).
// Smem rows: 32 halves = 64B = 4 chunks of 16B; chunk swizzle phys = ch ^ ((r>>1)&3).
// kb=16 address = kb=0 address XOR 32.
template <int HAS_BIAS>
__global__ void __launch_bounds__(256)
gemm_f16(const __half* __restrict__ A, const __half* __restrict__ Bp,
         float* __restrict__ Cp, int K,
         int lda, int ldb, int ldc,
         size_t sA, size_t sB, size_t sC,
         const float* __restrict__ rowBias, int rbStride,
         const float* __restrict__ colBias, int cbStride,
         const float* __restrict__ scalarBias) {
    extern __shared__ __align__(16) char dsm[];   // A: 4 x 8KB @0, B: 4 x 8KB @32768

    const int bz = blockIdx.z;
    A  += (size_t)bz * sA;
    Bp += (size_t)bz * sB;
    Cp += (size_t)bz * sC;
    const int tileM = blockIdx.y * 128;
    const int tileN = blockIdx.x * 128;
    const int tid = threadIdx.x;
    const int wid = tid >> 5, lane = tid & 31;
    const int warpM = (wid & 1) * 64;
    const int warpN = (wid >> 1) * 32;
    const int g = lane >> 2, tg = lane & 3;

    const unsigned smB = (unsigned)__cvta_generic_to_shared(dsm);

    // cp.async staging: 512 chunks/operand/stage, 2 per thread per operand
    unsigned off[2];
    const __half* aG[2];
    const __half* bG[2];
    #pragma unroll
    for (int t = 0; t < 2; t++) {
        int c = tid + t * 256;
        int r = c >> 2, ch = c & 3;
        off[t] = (unsigned)(r * 64 + ((ch ^ ((r >> 1) & 3)) << 4));
        aG[t] = A + (size_t)(tileM + r) * lda + ch * 8;
        bG[t] = Bp + (size_t)(tileN + r) * ldb + ch * 8;
    }

    auto prefetch = [&](int it, int st) {
        int k0 = it << 5;
        unsigned sa = smB + st * 8192;
        unsigned sb2 = smB + 32768 + st * 8192;
        #pragma unroll
        for (int t = 0; t < 2; t++) {
            cp16(sa + off[t], aG[t] + k0);
            cp16(sb2 + off[t], bG[t] + k0);
        }
    };

    // ldmatrix per-lane base addresses (stage 0, kb=0)
    unsigned addrA[4], addrB[2];
    #pragma unroll
    for (int mt = 0; mt < 4; mt++) {
        int row = warpM + mt * 16 + (lane & 15);
        int sec = lane >> 4;
        addrA[mt] = smB + (unsigned)(row * 64 + ((sec ^ ((row >> 1) & 3)) << 4));
    }
    #pragma unroll
    for (int p = 0; p < 2; p++) {
        int n = warpN + p * 16 + (lane & 7) + ((lane >> 4) << 3);
        int sec = (lane >> 3) & 1;
        addrB[p] = smB + 32768 + (unsigned)(n * 64 + ((sec ^ ((n >> 1) & 3)) << 4));
    }

    float acc[4][4][4] = {};
    const int nIter = K >> 5;

    prefetch(0, 0); cp_commit();
    prefetch(1, 1); cp_commit();

    for (int it = 0; it < nIter; it++) {
        const int st = it & 3;
        if (it + 2 < nIter) prefetch(it + 2, (it + 2) & 3);
        cp_commit();
        cp_wait2();
        __syncthreads();

        const unsigned sb0 = (unsigned)(st * 8192);
        #pragma unroll
        for (int kb2 = 0; kb2 < 2; kb2++) {
            const unsigned xv = kb2 << 5;
            unsigned af[4][4], bf[2][4];
            #pragma unroll
            for (int mt = 0; mt < 4; mt++)
                ldsm4(af[mt], (addrA[mt] + sb0) ^ xv);
            #pragma unroll
            for (int p = 0; p < 2; p++)
                ldsm4(bf[p], (addrB[p] + sb0) ^ xv);
            #pragma unroll
            for (int mt = 0; mt < 4; mt++)
                #pragma unroll
                for (int nt = 0; nt < 4; nt++)
                    mma_f16(acc[mt][nt], af[mt], &bf[nt >> 1][(nt & 1) * 2]);
        }
    }

    // ---- epilogue ----
    const float sb = (HAS_BIAS && scalarBias) ? __ldg(scalarBias) : 0.f;
    #pragma unroll
    for (int mt = 0; mt < 4; mt++) {
        int r0 = tileM + warpM + mt * 16 + g;
        int r1 = r0 + 8;
        float rb0 = HAS_BIAS ? rowBias[bz * rbStride + r0] + sb : 0.f;
        float rb1 = HAS_BIAS ? rowBias[bz * rbStride + r1] + sb : 0.f;
        #pragma unroll
        for (int nt = 0; nt < 4; nt++) {
            int c0 = tileN + warpN + nt * 8 + tg * 2;
            float cb0 = HAS_BIAS ? colBias[bz * cbStride + c0    ] : 0.f;
            float cb1 = HAS_BIAS ? colBias[bz * cbStride + c0 + 1] : 0.f;
            Cp[(size_t)r0 * ldc + c0    ] = acc[mt][nt][0] + rb0 + cb0;
            Cp[(size_t)r0 * ldc + c0 + 1] = acc[mt][nt][1] + rb0 + cb1;
            Cp[(size_t)r1 * ldc + c0    ] = acc[mt][nt][2] + rb1 + cb0;
            Cp[(size_t)r1 * ldc + c0 + 1] = acc[mt][nt][3] + rb1 + cb1;
        }
    }
}

// ---------------- softmax over c (axis=1): partial + combine (fp32 S) ----------------
__global__ void softc_partial(const float* __restrict__ S,
                              const float* __restrict__ cmask,
                              float* __restrict__ pm, float* __restrict__ ps) {
    int chunk = blockIdx.x, b = blockIdx.y;
    int q = threadIdx.x;
    constexpr int RB = C / NCH;
    const float* Sb = S + ((size_t)b * C + chunk * RB) * Q + q;
    const float* mcb = cmask + (size_t)b * C + chunk * RB;
    float m = -INFINITY, s = 0.f;
    #pragma unroll 4
    for (int c = 0; c < RB; c++) {
        float v = Sb[(size_t)c * Q] + (1.f - mcb[c]) * NEG_INF_F;
        float mn = fmaxf(m, v);
        s = s * __expf(m - mn) + __expf(v - mn);
        m = mn;
    }
    pm[(b * NCH + chunk) * Q + q] = m;
    ps[(b * NCH + chunk) * Q + q] = s;
}

__global__ void softc_combine(const float* __restrict__ pm,
                              const float* __restrict__ ps,
                              float* __restrict__ gm, float* __restrict__ ginv) {
    int b = blockIdx.x, q = threadIdx.x;
    float m = -INFINITY;
    #pragma unroll
    for (int ch = 0; ch < NCH; ch++)
        m = fmaxf(m, pm[(b * NCH + ch) * Q + q]);
    float s = 0.f;
    #pragma unroll
    for (int ch = 0; ch < NCH; ch++)
        s += ps[(b * NCH + ch) * Q + q] * __expf(pm[(b * NCH + ch) * Q + q] - m);
    gm[b * Q + q] = m;
    ginv[b * Q + q] = 1.f / s;
}

// ---------------- fused post: softmax_q -> Sh [C,Q] half; softc -> ScT [Q,C] half ----------------
__global__ void fused_post(const float* __restrict__ S,
                           __half* __restrict__ Sh, __half* __restrict__ ScT,
                           const float* __restrict__ cmask,
                           const float* __restrict__ qmask,
                           const float* __restrict__ gm,
                           const float* __restrict__ ginv) {
    __shared__ __half stg[128][20];
    int b = blockIdx.y;
    int cBase = blockIdx.x * 16;
    int wid = threadIdx.x >> 5, lane = threadIdx.x & 31;
    int c = cBase + wid;
    size_t base = ((size_t)b * C + c) * Q;
    float cadd = (1.f - cmask[b * C + c]) * NEG_INF_F;

    float raw[4], v[4];
    #pragma unroll
    for (int i = 0; i < 4; i++) {
        int q = lane + i * 32;
        raw[i] = S[base + q];
        v[i] = raw[i] + (1.f - qmask[b * Q + q]) * NEG_INF_F;
    }
    float m = fmaxf(fmaxf(v[0], v[1]), fmaxf(v[2], v[3]));
    #pragma unroll
    for (int o = 16; o > 0; o >>= 1) m = fmaxf(m, __shfl_xor_sync(0xffffffffu, m, o));
    float s = 0.f;
    #pragma unroll
    for (int i = 0; i < 4; i++) { v[i] = __expf(v[i] - m); s += v[i]; }
    #pragma unroll
    for (int o = 16; o > 0; o >>= 1) s += __shfl_xor_sync(0xffffffffu, s, o);
    float inv = 1.f / s;
    #pragma unroll
    for (int i = 0; i < 4; i++) {
        int q = lane + i * 32;
        Sh[base + q] = __float2half(v[i] * inv);
        stg[q][wid] = __float2half(__expf(raw[i] + cadd - gm[b * Q + q]) * ginv[b * Q + q]);
    }
    __syncthreads();
    int t = threadIdx.x;
    int q = t >> 2, part = t & 3;
    uint2 val = *(const uint2*)&stg[q][part * 4];
    *(uint2*)&ScT[((size_t)b * Q + q) * C + cBase + part * 4] = val;
}

// ---------------- launch ----------------
extern "C" void kernel_launch(void* const* d_in, const int* in_sizes, int n_in,
                              void* d_out, int out_size) {
    const float* x_context    = (const float*)d_in[0];  // B,C,H
    const float* x_query      = (const float*)d_in[1];  // B,Q,H
    const float* context_mask = (const float*)d_in[2];  // B,C
    const float* query_mask   = (const float*)d_in[3];  // B,Q
    const float* W0           = (const float*)d_in[4];
    const float* W1           = (const float*)d_in[5];
    const float* W2           = (const float*)d_in[6];
    const float* bias         = (const float*)d_in[7];
    float* out = (float*)d_out;                          // [c2q | q2c], each B*C*H

    __half *p_qwH, *p_xcH, *p_xcT, *p_xqT, *p_Sh, *p_ScT, *p_tmpT;
    float *p_S, *p_tmp, *p_sub0, *p_sub1, *p_pm, *p_ps, *p_gm, *p_ginv;
    cudaGetSymbolAddress((void**)&p_qwH,  g_qwH);
    cudaGetSymbolAddress((void**)&p_xcH,  g_xcH);
    cudaGetSymbolAddress((void**)&p_xcT,  g_xcT);
    cudaGetSymbolAddress((void**)&p_xqT,  g_xqT);
    cudaGetSymbolAddress((void**)&p_Sh,   g_Sh);
    cudaGetSymbolAddress((void**)&p_ScT,  g_ScT);
    cudaGetSymbolAddress((void**)&p_tmpT, g_tmpT);
    cudaGetSymbolAddress((void**)&p_S,    g_S);
    cudaGetSymbolAddress((void**)&p_tmp,  g_tmp);
    cudaGetSymbolAddress((void**)&p_sub0, g_sub0);
    cudaGetSymbolAddress((void**)&p_sub1, g_sub1);
    cudaGetSymbolAddress((void**)&p_pm,   g_pm);
    cudaGetSymbolAddress((void**)&p_ps,   g_ps);
    cudaGetSymbolAddress((void**)&p_gm,   g_gm);
    cudaGetSymbolAddress((void**)&p_ginv, g_ginv);

    const size_t BCH = (size_t)B * C * H;
    const int SMEM = 65536;

    cudaFuncSetAttribute(gemm_f16<1>, cudaFuncAttributeMaxDynamicSharedMemorySize, SMEM);
    cudaFuncSetAttribute(gemm_f16<0>, cudaFuncAttributeMaxDynamicSharedMemorySize, SMEM);

    // 1. prep + layout transposes
    prep_kernel<<<B * Q + B * C, 128>>>(x_query, x_context, W0, W1, W2,
                                        p_qwH, p_xcH, p_sub0, p_sub1);
    transpose_h<<<dim3(H / 32, Q / 32, B), dim3(32, 8)>>>(x_query, p_xqT, Q, H);
    transpose_h<<<dim3(H / 32, C / 32, B), dim3(32, 8)>>>(x_context, p_xcT, C, H);

    // 2. S = xcH @ qwH^T + sub1 + sub0 + bias   (M=C, N=Q, K=H)
    gemm_f16<1><<<dim3(Q / 128, C / 128, B), 256, SMEM>>>(
        p_xcH, p_qwH, p_S, H, H, H, Q,
        (size_t)C * H, (size_t)Q * H, (size_t)C * Q,
        p_sub1, C, p_sub0, Q, bias);

    // 3. softmaxes
    softc_partial<<<dim3(NCH, B), Q>>>(p_S, context_mask, p_pm, p_ps);
    softc_combine<<<B, Q>>>(p_pm, p_ps, p_gm, p_ginv);
    fused_post<<<dim3(C / 16, B), 512>>>(p_S, p_Sh, p_ScT, context_mask, query_mask,
                                         p_gm, p_ginv);

    // 4. tmp = Sc^T @ Xc   (M=Q, N=H, K=C): A=ScT [Q,C], B=xcT [H,C]
    gemm_f16<0><<<dim3(H / 128, Q / 128, B), 256, SMEM>>>(
        p_ScT, p_xcT, p_tmp, C, C, C, H,
        (size_t)Q * C, (size_t)H * C, (size_t)Q * H,
        nullptr, 0, nullptr, 0, nullptr);
    transpose_h<<<dim3(H / 32, Q / 32, B), dim3(32, 8)>>>(p_tmp, p_tmpT, Q, H);

    // 5. c2q = S_ @ Xq   (M=C, N=H, K=Q): A=Sh [C,Q], B=xqT [H,Q]
    gemm_f16<0><<<dim3(H / 128, C / 128, B), 256, SMEM>>>(
        p_Sh, p_xqT, out, Q, Q, Q, H,
        (size_t)C * Q, (size_t)H * Q, (size_t)C * H,
        nullptr, 0, nullptr, 0, nullptr);

    // 6. q2c = S_ @ tmp  (M=C, N=H, K=Q): A=Sh [C,Q], B=tmpT [H,Q]
    gemm_f16<0><<<dim3(H / 128, C / 128, B), 256, SMEM>>>(
        p_Sh, p_tmpT, out + BCH, Q, Q, Q, H,
        (size_t)C * Q, (size_t)H * Q, (size_t)C * H,
        nullptr, 0, nullptr, 0, nullptr);
}